// round 1
// baseline (speedup 1.0000x reference)
#include <cuda_runtime.h>

#define BS   2
#define SEQ  4096
#define HH   32
#define LLC  64            // chunk length == P == N == 64
#define CC   (SEQ/LLC)     // 64 chunks
#define RS   68            // smem row stride (floats), mult of 4 for float4
#define GSTR (HH*64)       // global stride between consecutive s for fixed (b,h)

// scratch: chunk states then prefix states, [b][c][h][p][n]
__device__ float g_states[(size_t)BS*CC*HH*64*64];

// ---------------------------------------------------------------------------
// K1: per (b,c,h) chunk: Y_diag into Y, chunk states into g_states
// ---------------------------------------------------------------------------
__global__ __launch_bounds__(256) void ssd_k1(
    const float* __restrict__ X, const float* __restrict__ A,
    const float* __restrict__ Bm, const float* __restrict__ Cm,
    float* __restrict__ Y)
{
    extern __shared__ float sm[];
    float* sX   = sm;                 // 64*RS
    float* sB   = sm + 64*RS;         // 64*RS
    float* sC   = sm + 2*64*RS;       // 64*RS, reused for masked G
    float* aA   = sm + 3*64*RS;       // 64
    float* el   = aA + 64;            // exp(+cum)
    float* einv = el + 64;            // exp(-cum)
    float* decs = einv + 64;          // exp(cum[63]-cum)
    float* acum = decs + 64;

    const int h = blockIdx.x, c = blockIdx.y, b = blockIdx.z;
    const int tid = threadIdx.x;
    const int base = ((b*SEQ + c*LLC)*HH + h)*64;

    // load 3 tiles (64 x 64 f32 each) via float4
    for (int i = tid; i < 1024; i += 256) {
        int row = i >> 4, c4 = (i & 15) << 2;
        int g = base + row*GSTR + c4;
        *(float4*)&sX[row*RS + c4] = *(const float4*)&X[g];
        *(float4*)&sB[row*RS + c4] = *(const float4*)&Bm[g];
        *(float4*)&sC[row*RS + c4] = *(const float4*)&Cm[g];
    }
    if (tid < 64) aA[tid] = A[(b*SEQ + c*LLC + tid)*HH + h];
    __syncthreads();

    // inclusive cumsum of A over the chunk + exp tables (one pass, 64 threads)
    if (tid < 64) {
        float s = 0.f, mine = 0.f;
        #pragma unroll
        for (int j = 0; j < 64; j++) { s += aA[j]; if (j == tid) mine = s; }
        acum[tid] = mine;
        el[tid]   = __expf(mine);
        einv[tid] = __expf(-mine);
        decs[tid] = __expf(s - mine);
    }
    __syncthreads();

    const int tx = tid & 15, ty = tid >> 4;
    const int r0 = ty << 2, c0 = tx << 2;

    // ---- matmul 1: G[l,s] = sum_n C[l,n]*B[s,n] ----
    float acc[4][4] = {};
    for (int k = 0; k < 64; k += 4) {
        float4 av[4], bv[4];
        #pragma unroll
        for (int i = 0; i < 4; i++) av[i] = *(const float4*)&sC[(r0+i)*RS + k];
        #pragma unroll
        for (int j = 0; j < 4; j++) bv[j] = *(const float4*)&sB[(c0+j)*RS + k];
        #pragma unroll
        for (int i = 0; i < 4; i++)
            #pragma unroll
            for (int j = 0; j < 4; j++)
                acc[i][j] += av[i].x*bv[j].x + av[i].y*bv[j].y
                           + av[i].z*bv[j].z + av[i].w*bv[j].w;
    }
    __syncthreads();   // all reads of sC done before overwrite

    // masked + decayed G into sC:  G*exp(cum[l]-cum[s]) for s<=l else 0
    #pragma unroll
    for (int i = 0; i < 4; i++) {
        int l = r0 + i;
        float eli = el[l];
        #pragma unroll
        for (int j = 0; j < 4; j++) {
            int s = c0 + j;
            sC[l*RS + s] = (s <= l) ? acc[i][j] * eli * einv[s] : 0.f;
        }
    }
    __syncthreads();

    // ---- matmul 2: Y_diag[l,p] = sum_s G[l,s] * X[s,p] ----
    float yv[4][4] = {};
    for (int s = 0; s < 64; s++) {
        float4 bx = *(const float4*)&sX[s*RS + c0];
        float bxa[4] = {bx.x, bx.y, bx.z, bx.w};
        #pragma unroll
        for (int i = 0; i < 4; i++) {
            float g = sC[(r0+i)*RS + s];
            #pragma unroll
            for (int j = 0; j < 4; j++) yv[i][j] += g * bxa[j];
        }
    }
    #pragma unroll
    for (int i = 0; i < 4; i++) {
        float4 v = make_float4(yv[i][0], yv[i][1], yv[i][2], yv[i][3]);
        *(float4*)&Y[base + (r0+i)*GSTR + c0] = v;
    }

    // ---- matmul 3: states[p,n] = sum_l dec[l]*B[l,n]*X[l,p] ----
    float st[4][4] = {};
    for (int l = 0; l < 64; l++) {
        float dec = decs[l];
        float4 ax = *(const float4*)&sX[l*RS + r0];   // p block (broadcast)
        float4 bb = *(const float4*)&sB[l*RS + c0];   // n block
        float ba[4] = {bb.x*dec, bb.y*dec, bb.z*dec, bb.w*dec};
        float aa[4] = {ax.x, ax.y, ax.z, ax.w};
        #pragma unroll
        for (int i = 0; i < 4; i++)
            #pragma unroll
            for (int j = 0; j < 4; j++)
                st[i][j] += aa[i] * ba[j];
    }
    const int sbase = ((b*CC + c)*HH + h)*4096;
    #pragma unroll
    for (int i = 0; i < 4; i++) {
        float4 v = make_float4(st[i][0], st[i][1], st[i][2], st[i][3]);
        *(float4*)&g_states[sbase + (r0+i)*64 + c0] = v;
    }
}

// ---------------------------------------------------------------------------
// K2: inter-chunk scan per (b,h): overwrite g_states with prefix states
// ---------------------------------------------------------------------------
__global__ __launch_bounds__(512) void ssd_k2(const float* __restrict__ A)
{
    __shared__ float ea[CC];
    const int bh = blockIdx.x;
    const int b = bh >> 5, h = bh & 31;
    const int tid = threadIdx.x;

    if (tid < CC) {
        float s = 0.f;
        int abase = (b*SEQ + tid*LLC)*HH + h;
        for (int l = 0; l < LLC; l++) s += A[abase + l*HH];
        ea[tid] = __expf(s);
    }
    __syncthreads();

    float run[8] = {};
    int off = ((b*CC)*HH + h)*4096 + tid;   // chunk 0
    for (int z = 0; z < CC; z++) {
        float e = ea[z];
        #pragma unroll
        for (int k = 0; k < 8; k++) {
            float tmp = g_states[off + k*512];
            g_states[off + k*512] = run[k];       // prefix state entering chunk z
            run[k] = run[k]*e + tmp;
        }
        off += HH*4096;
    }
}

// ---------------------------------------------------------------------------
// K3: Y_off[l,p] = exp(cum[l]) * sum_n C[l,n]*state[p,n], accumulated into Y
// ---------------------------------------------------------------------------
__global__ __launch_bounds__(256) void ssd_k3(
    const float* __restrict__ A, const float* __restrict__ Cm,
    float* __restrict__ Y)
{
    extern __shared__ float sm[];
    float* sC = sm;               // 64*RS
    float* sS = sm + 64*RS;       // 64*RS
    float* aA = sm + 2*64*RS;     // 64
    float* el = aA + 64;          // 64

    const int h = blockIdx.x, c = blockIdx.y, b = blockIdx.z;
    const int tid = threadIdx.x;
    const int base = ((b*SEQ + c*LLC)*HH + h)*64;
    const int sbase = ((b*CC + c)*HH + h)*4096;

    for (int i = tid; i < 1024; i += 256) {
        int row = i >> 4, c4 = (i & 15) << 2;
        *(float4*)&sC[row*RS + c4] = *(const float4*)&Cm[base + row*GSTR + c4];
        *(float4*)&sS[row*RS + c4] = *(const float4*)&g_states[sbase + row*64 + c4];
    }
    if (tid < 64) aA[tid] = A[(b*SEQ + c*LLC + tid)*HH + h];
    __syncthreads();
    if (tid < 64) {
        float s = 0.f, mine = 0.f;
        #pragma unroll
        for (int j = 0; j < 64; j++) { s += aA[j]; if (j == tid) mine = s; }
        el[tid] = __expf(mine);
    }
    __syncthreads();

    const int tx = tid & 15, ty = tid >> 4;
    const int r0 = ty << 2, c0 = tx << 2;    // r0: l rows, c0: p cols

    float acc[4][4] = {};
    for (int k = 0; k < 64; k += 4) {
        float4 av[4], bv[4];
        #pragma unroll
        for (int i = 0; i < 4; i++) av[i] = *(const float4*)&sC[(r0+i)*RS + k];
        #pragma unroll
        for (int j = 0; j < 4; j++) bv[j] = *(const float4*)&sS[(c0+j)*RS + k];
        #pragma unroll
        for (int i = 0; i < 4; i++)
            #pragma unroll
            for (int j = 0; j < 4; j++)
                acc[i][j] += av[i].x*bv[j].x + av[i].y*bv[j].y
                           + av[i].z*bv[j].z + av[i].w*bv[j].w;
    }

    #pragma unroll
    for (int i = 0; i < 4; i++) {
        int l = r0 + i;
        float sc = el[l];
        float4 o = *(float4*)&Y[base + l*GSTR + c0];
        o.x += sc*acc[i][0]; o.y += sc*acc[i][1];
        o.z += sc*acc[i][2]; o.w += sc*acc[i][3];
        *(float4*)&Y[base + l*GSTR + c0] = o;
    }
}

// ---------------------------------------------------------------------------
extern "C" void kernel_launch(void* const* d_in, const int* in_sizes, int n_in,
                              void* d_out, int out_size)
{
    const float* X  = (const float*)d_in[0];
    const float* A  = (const float*)d_in[1];
    const float* Bm = (const float*)d_in[2];
    const float* Cm = (const float*)d_in[3];
    float* Y = (float*)d_out;

    const size_t sm1 = (size_t)(3*64*RS + 5*64) * sizeof(float);   // ~53.5 KB
    const size_t sm3 = (size_t)(2*64*RS + 2*64) * sizeof(float);   // ~35 KB
    cudaFuncSetAttribute(ssd_k1, cudaFuncAttributeMaxDynamicSharedMemorySize, (int)sm1);
    cudaFuncSetAttribute(ssd_k3, cudaFuncAttributeMaxDynamicSharedMemorySize, (int)sm3);

    dim3 grid(HH, CC, BS);
    ssd_k1<<<grid, 256, sm1>>>(X, A, Bm, Cm, Y);
    ssd_k2<<<BS*HH, 512>>>(A);
    ssd_k3<<<grid, 256, sm3>>>(A, Cm, Y);
}

// round 2
// speedup vs baseline: 1.1223x; 1.1223x over previous
#include <cuda_runtime.h>

#define BS   2
#define SEQ  4096
#define HH   32
#define LLC  64            // chunk length == P == N == 64
#define CC   (SEQ/LLC)     // 64 chunks
#define RS   68            // smem row stride (floats), mult of 4 for float4
#define GSTR (HH*64)       // global stride between consecutive s for fixed (b,h)

// scratch: chunk states [b][c][h][p][n], prefix states transposed [b][c][h][n][p]
__device__ float g_states[(size_t)BS*CC*HH*64*64];
__device__ float g_prefix[(size_t)BS*CC*HH*64*64];

// ---- packed fp32x2 helpers (FFMA2: ptxas never emits this from C++) ----
typedef unsigned long long u64;
__device__ __forceinline__ u64 pk2(float x, float y) {
    u64 r; asm("mov.b64 %0,{%1,%2};" : "=l"(r) : "f"(x), "f"(y)); return r;
}
__device__ __forceinline__ void fma2(u64& d, u64 a, u64 b) {
    asm("fma.rn.f32x2 %0,%1,%2,%0;" : "+l"(d) : "l"(a), "l"(b));
}
__device__ __forceinline__ float2 upk(u64 v) {
    float2 f; asm("mov.b64 {%0,%1},%2;" : "=f"(f.x), "=f"(f.y) : "l"(v)); return f;
}

// ---------------------------------------------------------------------------
// K1: per (b,c,h) chunk: Y_diag into Y, chunk states into g_states
// ---------------------------------------------------------------------------
__global__ __launch_bounds__(256) void ssd_k1(
    const float* __restrict__ X, const float* __restrict__ A,
    const float* __restrict__ Bm, const float* __restrict__ Cm,
    float* __restrict__ Y)
{
    extern __shared__ float sm[];
    float* sX   = sm;                 // 64*RS  [s][p]
    float* sB   = sm + 64*RS;         // 64*RS  [s][n]
    float* sC   = sm + 2*64*RS;       // 64*RS  [l][n]
    float* sBt  = sm + 3*64*RS;       // 64*RS  [n][s], reused for masked G [l][s]
    float* aA   = sm + 4*64*RS;       // 64
    float* el   = aA + 64;            // exp(+cum)
    float* einv = el + 64;            // exp(-cum)
    float* decs = einv + 64;          // exp(cum[63]-cum)

    const int h = blockIdx.x, c = blockIdx.y, b = blockIdx.z;
    const int tid = threadIdx.x;
    const int base = ((b*SEQ + c*LLC)*HH + h)*64;

    // load 3 tiles (64 x 64 f32 each) via float4 (coalesced)
    for (int i = tid; i < 1024; i += 256) {
        int row = i >> 4, c4 = (i & 15) << 2;
        int g = base + row*GSTR + c4;
        *(float4*)&sX[row*RS + c4] = *(const float4*)&X[g];
        *(float4*)&sB[row*RS + c4] = *(const float4*)&Bm[g];
        *(float4*)&sC[row*RS + c4] = *(const float4*)&Cm[g];
    }
    if (tid < 64) aA[tid] = A[(b*SEQ + c*LLC + tid)*HH + h];
    __syncthreads();

    // transpose B into sBt[n][s] (one-time; writes have conflicts but amortized)
    for (int i = tid; i < 1024; i += 256) {
        int row = i >> 4, c4 = (i & 15) << 2;
        float4 v = *(const float4*)&sB[row*RS + c4];
        sBt[(c4+0)*RS + row] = v.x;
        sBt[(c4+1)*RS + row] = v.y;
        sBt[(c4+2)*RS + row] = v.z;
        sBt[(c4+3)*RS + row] = v.w;
    }
    // cumsum of A + exp tables
    if (tid < 64) {
        float s = 0.f, mine = 0.f;
        #pragma unroll
        for (int j = 0; j < 64; j++) { s += aA[j]; if (j == tid) mine = s; }
        el[tid]   = __expf(mine);
        einv[tid] = __expf(-mine);
        decs[tid] = __expf(s - mine);
    }
    __syncthreads();

    const int tx = tid & 15, ty = tid >> 4;
    const int r0 = ty << 2, c0 = tx << 2;

    // ---- mm1: G[l,s] = sum_n C[l,n]*Bt[n,s]  (outer-product, conflict-free) ----
    u64 acc[4][2] = {};
    #pragma unroll 4
    for (int n4 = 0; n4 < 64; n4 += 4) {
        float4 a4[4];
        #pragma unroll
        for (int i = 0; i < 4; i++) a4[i] = *(const float4*)&sC[(r0+i)*RS + n4];
        #pragma unroll
        for (int u = 0; u < 4; u++) {
            float4 bt = *(const float4*)&sBt[(n4+u)*RS + c0];
            u64 b01 = pk2(bt.x, bt.y), b23 = pk2(bt.z, bt.w);
            #pragma unroll
            for (int i = 0; i < 4; i++) {
                float a = (u==0) ? a4[i].x : (u==1) ? a4[i].y : (u==2) ? a4[i].z : a4[i].w;
                u64 a2 = pk2(a, a);
                fma2(acc[i][0], a2, b01);
                fma2(acc[i][1], a2, b23);
            }
        }
    }
    __syncthreads();   // all reads of sBt done before overwrite

    // masked + decayed G into sBt[l][s]:  G*exp(cum[l])*exp(-cum[s]) for s<=l
    #pragma unroll
    for (int i = 0; i < 4; i++) {
        int l = r0 + i;
        float eli = el[l];
        float2 g01 = upk(acc[i][0]), g23 = upk(acc[i][1]);
        float gv[4] = {g01.x, g01.y, g23.x, g23.y};
        float4 out;
        float* o = (float*)&out;
        #pragma unroll
        for (int j = 0; j < 4; j++) {
            int s = c0 + j;
            o[j] = (s <= l) ? gv[j] * eli * einv[s] : 0.f;
        }
        *(float4*)&sBt[l*RS + c0] = out;
    }
    __syncthreads();

    // ---- mm2: Y_diag[l,p] = sum_s G[l,s]*X[s,p] ----
    u64 yacc[4][2] = {};
    #pragma unroll 4
    for (int s = 0; s < 64; s++) {
        float4 bx = *(const float4*)&sX[s*RS + c0];
        u64 b01 = pk2(bx.x, bx.y), b23 = pk2(bx.z, bx.w);
        #pragma unroll
        for (int i = 0; i < 4; i++) {
            float g = sBt[(r0+i)*RS + s];
            u64 g2 = pk2(g, g);
            fma2(yacc[i][0], g2, b01);
            fma2(yacc[i][1], g2, b23);
        }
    }
    #pragma unroll
    for (int i = 0; i < 4; i++) {
        float2 y01 = upk(yacc[i][0]), y23 = upk(yacc[i][1]);
        *(float4*)&Y[base + (r0+i)*GSTR + c0] = make_float4(y01.x, y01.y, y23.x, y23.y);
    }

    // ---- mm3: states[p,n] = sum_l dec[l]*X[l,p]*B[l,n] ----
    u64 st[4][2] = {};
    #pragma unroll 4
    for (int l = 0; l < 64; l++) {
        float dec = decs[l];
        float4 bb = *(const float4*)&sB[l*RS + c0];   // n block (contiguous)
        float4 ax = *(const float4*)&sX[l*RS + r0];   // p block (broadcast)
        u64 b01 = pk2(bb.x*dec, bb.y*dec), b23 = pk2(bb.z*dec, bb.w*dec);
        float aa[4] = {ax.x, ax.y, ax.z, ax.w};
        #pragma unroll
        for (int i = 0; i < 4; i++) {
            u64 a2 = pk2(aa[i], aa[i]);
            fma2(st[i][0], a2, b01);
            fma2(st[i][1], a2, b23);
        }
    }
    const int sbase = ((b*CC + c)*HH + h)*4096;
    #pragma unroll
    for (int i = 0; i < 4; i++) {
        float2 s01 = upk(st[i][0]), s23 = upk(st[i][1]);
        *(float4*)&g_states[sbase + (r0+i)*64 + c0] =
            make_float4(s01.x, s01.y, s23.x, s23.y);
    }
}

// ---------------------------------------------------------------------------
// K2: inter-chunk scan per (b,h): g_states [p][n] -> g_prefix transposed [n][p]
// ---------------------------------------------------------------------------
__global__ __launch_bounds__(512) void ssd_k2(const float* __restrict__ A)
{
    __shared__ float ea[CC];
    const int bh = blockIdx.x;
    const int b = bh >> 5, h = bh & 31;
    const int tid = threadIdx.x;

    if (tid < CC) {
        float s = 0.f;
        int abase = (b*SEQ + tid*LLC)*HH + h;
        for (int l = 0; l < LLC; l++) s += A[abase + l*HH];
        ea[tid] = __expf(s);
    }
    __syncthreads();

    float run[8] = {};
    int roff[8], woff[8];
    #pragma unroll
    for (int k = 0; k < 8; k++) {
        int e = tid + k*512;                    // e = p*64 + n
        roff[k] = e;
        woff[k] = ((e & 63) << 6) + (e >> 6);   // transposed: n*64 + p
    }
    int cbase = ((b*CC)*HH + h)*4096;
    for (int z = 0; z < CC; z++) {
        float e = ea[z];
        #pragma unroll
        for (int k = 0; k < 8; k++) {
            float tmp = g_states[cbase + roff[k]];
            g_prefix[cbase + woff[k]] = run[k];   // prefix entering chunk z
            run[k] = run[k]*e + tmp;
        }
        cbase += HH*4096;
    }
}

// ---------------------------------------------------------------------------
// K3: Y_off[l,p] = exp(cum[l]) * sum_n C[l,n]*St[n,p], accumulated into Y
// ---------------------------------------------------------------------------
__global__ __launch_bounds__(256) void ssd_k3(
    const float* __restrict__ A, const float* __restrict__ Cm,
    float* __restrict__ Y)
{
    extern __shared__ float sm[];
    float* sC  = sm;              // 64*RS  [l][n]
    float* sSt = sm + 64*RS;      // 64*RS  [n][p]
    float* aA  = sm + 2*64*RS;    // 64
    float* el  = aA + 64;         // 64

    const int h = blockIdx.x, c = blockIdx.y, b = blockIdx.z;
    const int tid = threadIdx.x;
    const int base = ((b*SEQ + c*LLC)*HH + h)*64;
    const int sbase = ((b*CC + c)*HH + h)*4096;

    for (int i = tid; i < 1024; i += 256) {
        int row = i >> 4, c4 = (i & 15) << 2;
        *(float4*)&sC[row*RS + c4]  = *(const float4*)&Cm[base + row*GSTR + c4];
        *(float4*)&sSt[row*RS + c4] = *(const float4*)&g_prefix[sbase + row*64 + c4];
    }
    if (tid < 64) aA[tid] = A[(b*SEQ + c*LLC + tid)*HH + h];
    __syncthreads();
    if (tid < 64) {
        float s = 0.f, mine = 0.f;
        #pragma unroll
        for (int j = 0; j < 64; j++) { s += aA[j]; if (j == tid) mine = s; }
        el[tid] = __expf(mine);
    }
    __syncthreads();

    const int tx = tid & 15, ty = tid >> 4;
    const int r0 = ty << 2, c0 = tx << 2;    // r0: l rows, c0: p cols

    u64 acc[4][2] = {};
    #pragma unroll 4
    for (int n4 = 0; n4 < 64; n4 += 4) {
        float4 a4[4];
        #pragma unroll
        for (int i = 0; i < 4; i++) a4[i] = *(const float4*)&sC[(r0+i)*RS + n4];
        #pragma unroll
        for (int u = 0; u < 4; u++) {
            float4 bt = *(const float4*)&sSt[(n4+u)*RS + c0];
            u64 b01 = pk2(bt.x, bt.y), b23 = pk2(bt.z, bt.w);
            #pragma unroll
            for (int i = 0; i < 4; i++) {
                float a = (u==0) ? a4[i].x : (u==1) ? a4[i].y : (u==2) ? a4[i].z : a4[i].w;
                u64 a2 = pk2(a, a);
                fma2(acc[i][0], a2, b01);
                fma2(acc[i][1], a2, b23);
            }
        }
    }

    #pragma unroll
    for (int i = 0; i < 4; i++) {
        int l = r0 + i;
        float sc = el[l];
        float2 a01 = upk(acc[i][0]), a23 = upk(acc[i][1]);
        float4 o = *(float4*)&Y[base + l*GSTR + c0];
        o.x += sc*a01.x; o.y += sc*a01.y;
        o.z += sc*a23.x; o.w += sc*a23.y;
        *(float4*)&Y[base + l*GSTR + c0] = o;
    }
}

// ---------------------------------------------------------------------------
extern "C" void kernel_launch(void* const* d_in, const int* in_sizes, int n_in,
                              void* d_out, int out_size)
{
    const float* X  = (const float*)d_in[0];
    const float* A  = (const float*)d_in[1];
    const float* Bm = (const float*)d_in[2];
    const float* Cm = (const float*)d_in[3];
    float* Y = (float*)d_out;

    const size_t sm1 = (size_t)(4*64*RS + 4*64) * sizeof(float);   // ~70 KB
    const size_t sm3 = (size_t)(2*64*RS + 2*64) * sizeof(float);   // ~35 KB
    cudaFuncSetAttribute(ssd_k1, cudaFuncAttributeMaxDynamicSharedMemorySize, (int)sm1);
    cudaFuncSetAttribute(ssd_k3, cudaFuncAttributeMaxDynamicSharedMemorySize, (int)sm3);

    dim3 grid(HH, CC, BS);
    ssd_k1<<<grid, 256, sm1>>>(X, A, Bm, Cm, Y);
    ssd_k2<<<BS*HH, 512>>>(A);
    ssd_k3<<<grid, 256, sm3>>>(A, Cm, Y);
}

// round 3
// speedup vs baseline: 1.7132x; 1.5265x over previous
#include <cuda_runtime.h>

#define BS   2
#define SEQ  4096
#define HH   32
#define LLC  64
#define CC   (SEQ/LLC)
#define RS   68            // smem row stride (floats)
#define GSTR (HH*64)

// scratch: chunk states [b][c][h][p][n]; prefix states same layout
__device__ float g_states[(size_t)BS*CC*HH*64*64];
__device__ float g_prefix[(size_t)BS*CC*HH*64*64];

typedef unsigned long long u64;
__device__ __forceinline__ u64 pk2(float x, float y) {
    u64 r; asm("mov.b64 %0,{%1,%2};" : "=l"(r) : "f"(x), "f"(y)); return r;
}
__device__ __forceinline__ void fma2(u64& d, u64 a, u64 b) {
    asm("fma.rn.f32x2 %0,%1,%2,%0;" : "+l"(d) : "l"(a), "l"(b));
}
__device__ __forceinline__ float2 upk(u64 v) {
    float2 f; asm("mov.b64 {%0,%1},%2;" : "=f"(f.x), "=f"(f.y) : "l"(v)); return f;
}
__device__ __forceinline__ float comp4(float4 v, int u) {
    return (u==0) ? v.x : (u==1) ? v.y : (u==2) ? v.z : v.w;
}

// ---------------------------------------------------------------------------
// K1: 128 threads, 8x4 per-thread tiles. Y_diag -> Y, chunk states -> g_states
// ---------------------------------------------------------------------------
__global__ __launch_bounds__(128) void ssd_k1(
    const float* __restrict__ X, const float* __restrict__ A,
    const float* __restrict__ Bm, const float* __restrict__ Cm,
    float* __restrict__ Y)
{
    extern __shared__ float sm[];
    float* sX   = sm;                 // [s][p]
    float* sB   = sm + 64*RS;         // [l][n] (later scaled by decs[l])
    float* sC   = sm + 2*64*RS;       // [l][n]
    float* sBt  = sm + 3*64*RS;       // [n][s], reused for masked G [l][s]
    float* aA   = sm + 4*64*RS;
    float* el   = aA + 64;
    float* einv = el + 64;
    float* decs = einv + 64;

    const int h = blockIdx.x, c = blockIdx.y, b = blockIdx.z;
    const int tid = threadIdx.x;
    const int base = ((b*SEQ + c*LLC)*HH + h)*64;

    #pragma unroll
    for (int i = tid; i < 1024; i += 128) {
        int row = i >> 4, c4 = (i & 15) << 2;
        int g = base + row*GSTR + c4;
        *(float4*)&sX[row*RS + c4] = *(const float4*)&X[g];
        *(float4*)&sB[row*RS + c4] = *(const float4*)&Bm[g];
        *(float4*)&sC[row*RS + c4] = *(const float4*)&Cm[g];
    }
    if (tid < 64) aA[tid] = A[(b*SEQ + c*LLC + tid)*HH + h];
    __syncthreads();

    // transpose B -> sBt[n][s]
    #pragma unroll
    for (int i = tid; i < 1024; i += 128) {
        int row = i >> 4, c4 = (i & 15) << 2;
        float4 v = *(const float4*)&sB[row*RS + c4];
        sBt[(c4+0)*RS + row] = v.x;
        sBt[(c4+1)*RS + row] = v.y;
        sBt[(c4+2)*RS + row] = v.z;
        sBt[(c4+3)*RS + row] = v.w;
    }
    if (tid < 64) {
        float s = 0.f, mine = 0.f;
        #pragma unroll
        for (int j = 0; j < 64; j++) { s += aA[j]; if (j == tid) mine = s; }
        el[tid]   = __expf(mine);
        einv[tid] = __expf(-mine);
        decs[tid] = __expf(s - mine);
    }
    __syncthreads();

    const int tx = tid & 15, ty = tid >> 4;
    const int r0 = ty << 3, c0 = tx << 2;    // 8 rows, 4 cols

    // ---- mm1: G[l,s] = sum_n C[l,n]*Bt[n,s] ----
    u64 acc[8][2] = {};
    #pragma unroll
    for (int k4 = 0; k4 < 64; k4 += 4) {
        float4 a[8];
        #pragma unroll
        for (int i = 0; i < 8; i++) a[i] = *(const float4*)&sC[(r0+i)*RS + k4];
        #pragma unroll
        for (int u = 0; u < 4; u++) {
            ulonglong2 bt = *(const ulonglong2*)&sBt[(k4+u)*RS + c0];
            #pragma unroll
            for (int i = 0; i < 8; i++) {
                float av = comp4(a[i], u);
                u64 a2 = pk2(av, av);
                fma2(acc[i][0], a2, bt.x);
                fma2(acc[i][1], a2, bt.y);
            }
        }
    }
    __syncthreads();   // reads of sBt done

    // masked+decayed G into sBt[l][s]; also scale sB rows by decs (for mm3)
    #pragma unroll
    for (int i = 0; i < 8; i++) {
        int l = r0 + i;
        float eli = el[l];
        float2 g01 = upk(acc[i][0]), g23 = upk(acc[i][1]);
        float gv[4] = {g01.x, g01.y, g23.x, g23.y};
        float4 out;
        float* o = (float*)&out;
        #pragma unroll
        for (int j = 0; j < 4; j++) {
            int s = c0 + j;
            o[j] = (s <= l) ? gv[j] * eli * einv[s] : 0.f;
        }
        *(float4*)&sBt[l*RS + c0] = out;
    }
    #pragma unroll
    for (int i = tid; i < 1024; i += 128) {
        int row = i >> 4, c4 = (i & 15) << 2;
        float d = decs[row];
        float4 v = *(const float4*)&sB[row*RS + c4];
        v.x *= d; v.y *= d; v.z *= d; v.w *= d;
        *(float4*)&sB[row*RS + c4] = v;
    }
    __syncthreads();

    // ---- mm2: Y_diag[l,p] = sum_{s<=l} G[l,s]*X[s,p]; G zero above diag ----
    u64 y[8][2] = {};
    const int sMax = r0 + 8;
    for (int s4 = 0; s4 < sMax; s4 += 4) {
        float4 g[8];
        #pragma unroll
        for (int i = 0; i < 8; i++) g[i] = *(const float4*)&sBt[(r0+i)*RS + s4];
        #pragma unroll
        for (int u = 0; u < 4; u++) {
            ulonglong2 bx = *(const ulonglong2*)&sX[(s4+u)*RS + c0];
            #pragma unroll
            for (int i = 0; i < 8; i++) {
                float gv = comp4(g[i], u);
                u64 g2 = pk2(gv, gv);
                fma2(y[i][0], g2, bx.x);
                fma2(y[i][1], g2, bx.y);
            }
        }
    }
    #pragma unroll
    for (int i = 0; i < 8; i++) {
        float2 y01 = upk(y[i][0]), y23 = upk(y[i][1]);
        *(float4*)&Y[base + (r0+i)*GSTR + c0] = make_float4(y01.x, y01.y, y23.x, y23.y);
    }

    // ---- mm3: states[p,n] = sum_l X[l,p] * (dec[l]*B[l,n]) ----
    u64 st[8][2] = {};
    #pragma unroll 4
    for (int l = 0; l < 64; l++) {
        ulonglong2 bb = *(const ulonglong2*)&sB[l*RS + c0];
        float4 ax0 = *(const float4*)&sX[l*RS + r0];
        float4 ax1 = *(const float4*)&sX[l*RS + r0 + 4];
        float aa[8] = {ax0.x, ax0.y, ax0.z, ax0.w, ax1.x, ax1.y, ax1.z, ax1.w};
        #pragma unroll
        for (int i = 0; i < 8; i++) {
            u64 a2 = pk2(aa[i], aa[i]);
            fma2(st[i][0], a2, bb.x);
            fma2(st[i][1], a2, bb.y);
        }
    }
    const int sbase = ((b*CC + c)*HH + h)*4096;
    #pragma unroll
    for (int i = 0; i < 8; i++) {
        float2 s01 = upk(st[i][0]), s23 = upk(st[i][1]);
        *(float4*)&g_states[sbase + (r0+i)*64 + c0] =
            make_float4(s01.x, s01.y, s23.x, s23.y);
    }
}

// ---------------------------------------------------------------------------
// K2: inter-chunk scan per (b,h), fully coalesced float4, layout unchanged
// ---------------------------------------------------------------------------
__global__ __launch_bounds__(512) void ssd_k2(const float* __restrict__ A)
{
    __shared__ float ea[CC];
    const int bh = blockIdx.x;
    const int b = bh >> 5, h = bh & 31;
    const int tid = threadIdx.x;

    if (tid < CC) {
        float s = 0.f;
        int abase = (b*SEQ + tid*LLC)*HH + h;
        for (int l = 0; l < LLC; l++) s += A[abase + l*HH];
        ea[tid] = __expf(s);
    }
    __syncthreads();

    float run[8] = {};
    int off = ((b*CC)*HH + h)*4096 + tid*8;
    for (int z = 0; z < CC; z++) {
        float e = ea[z];
        float4 v0 = *(const float4*)&g_states[off];
        float4 v1 = *(const float4*)&g_states[off + 4];
        *(float4*)&g_prefix[off]     = make_float4(run[0], run[1], run[2], run[3]);
        *(float4*)&g_prefix[off + 4] = make_float4(run[4], run[5], run[6], run[7]);
        run[0] = run[0]*e + v0.x; run[1] = run[1]*e + v0.y;
        run[2] = run[2]*e + v0.z; run[3] = run[3]*e + v0.w;
        run[4] = run[4]*e + v1.x; run[5] = run[5]*e + v1.y;
        run[6] = run[6]*e + v1.z; run[7] = run[7]*e + v1.w;
        off += HH*4096;
    }
}

// ---------------------------------------------------------------------------
// K3: Y_off[l,p] = exp(cum[l]) * sum_n C[l,n]*St[n,p], accumulate into Y
// ---------------------------------------------------------------------------
__global__ __launch_bounds__(128) void ssd_k3(
    const float* __restrict__ A, const float* __restrict__ Cm,
    float* __restrict__ Y)
{
    extern __shared__ float sm[];
    float* sC  = sm;              // [l][n]
    float* sS  = sm + 64*RS;      // [p][n]
    float* sSt = sm + 2*64*RS;    // [n][p]
    float* aA  = sm + 3*64*RS;
    float* el  = aA + 64;

    const int h = blockIdx.x, c = blockIdx.y, b = blockIdx.z;
    const int tid = threadIdx.x;
    const int base = ((b*SEQ + c*LLC)*HH + h)*64;
    const int sbase = ((b*CC + c)*HH + h)*4096;

    #pragma unroll
    for (int i = tid; i < 1024; i += 128) {
        int row = i >> 4, c4 = (i & 15) << 2;
        *(float4*)&sC[row*RS + c4] = *(const float4*)&Cm[base + row*GSTR + c4];
        *(float4*)&sS[row*RS + c4] = *(const float4*)&g_prefix[sbase + row*64 + c4];
    }
    if (tid < 64) aA[tid] = A[(b*SEQ + c*LLC + tid)*HH + h];
    __syncthreads();

    // transpose S -> sSt[n][p]
    #pragma unroll
    for (int i = tid; i < 1024; i += 128) {
        int row = i >> 4, c4 = (i & 15) << 2;
        float4 v = *(const float4*)&sS[row*RS + c4];
        sSt[(c4+0)*RS + row] = v.x;
        sSt[(c4+1)*RS + row] = v.y;
        sSt[(c4+2)*RS + row] = v.z;
        sSt[(c4+3)*RS + row] = v.w;
    }
    if (tid < 64) {
        float s = 0.f, mine = 0.f;
        #pragma unroll
        for (int j = 0; j < 64; j++) { s += aA[j]; if (j == tid) mine = s; }
        el[tid] = __expf(mine);
    }
    __syncthreads();

    const int tx = tid & 15, ty = tid >> 4;
    const int r0 = ty << 3, c0 = tx << 2;

    u64 acc[8][2] = {};
    #pragma unroll
    for (int n4 = 0; n4 < 64; n4 += 4) {
        float4 a[8];
        #pragma unroll
        for (int i = 0; i < 8; i++) a[i] = *(const float4*)&sC[(r0+i)*RS + n4];
        #pragma unroll
        for (int u = 0; u < 4; u++) {
            ulonglong2 bt = *(const ulonglong2*)&sSt[(n4+u)*RS + c0];
            #pragma unroll
            for (int i = 0; i < 8; i++) {
                float av = comp4(a[i], u);
                u64 a2 = pk2(av, av);
                fma2(acc[i][0], a2, bt.x);
                fma2(acc[i][1], a2, bt.y);
            }
        }
    }

    #pragma unroll
    for (int i = 0; i < 8; i++) {
        int l = r0 + i;
        float sc = el[l];
        float2 a01 = upk(acc[i][0]), a23 = upk(acc[i][1]);
        float4 o = *(float4*)&Y[base + l*GSTR + c0];
        o.x += sc*a01.x; o.y += sc*a01.y;
        o.z += sc*a23.x; o.w += sc*a23.y;
        *(float4*)&Y[base + l*GSTR + c0] = o;
    }
}

// ---------------------------------------------------------------------------
extern "C" void kernel_launch(void* const* d_in, const int* in_sizes, int n_in,
                              void* d_out, int out_size)
{
    const float* X  = (const float*)d_in[0];
    const float* A  = (const float*)d_in[1];
    const float* Bm = (const float*)d_in[2];
    const float* Cm = (const float*)d_in[3];
    float* Y = (float*)d_out;

    const size_t sm1 = (size_t)(4*64*RS + 4*64) * sizeof(float);   // ~70.7 KB
    const size_t sm3 = (size_t)(3*64*RS + 2*64) * sizeof(float);   // ~52.7 KB
    cudaFuncSetAttribute(ssd_k1, cudaFuncAttributeMaxDynamicSharedMemorySize, (int)sm1);
    cudaFuncSetAttribute(ssd_k3, cudaFuncAttributeMaxDynamicSharedMemorySize, (int)sm3);

    dim3 grid(HH, CC, BS);
    ssd_k1<<<grid, 128, sm1>>>(X, A, Bm, Cm, Y);
    ssd_k2<<<BS*HH, 512>>>(A);
    ssd_k3<<<grid, 128, sm3>>>(A, Cm, Y);
}

// round 5
// speedup vs baseline: 2.0513x; 1.1973x over previous
#include <cuda_runtime.h>
#include <cstdint>

#define BS   2
#define SEQ  4096
#define HH   32
#define LLC  64
#define CC   (SEQ/LLC)   // 64
#define RS   68          // smem row stride (4B elems)
#define GSTR (HH*64)

__device__ float g_states[(size_t)BS*CC*HH*64*64]; // [b][c][h][p][n]
__device__ float g_prefix[(size_t)BS*CC*HH*64*64];

typedef unsigned int u32;

__device__ __forceinline__ u32 cvt_tf32(float f){
    u32 u; asm("cvt.rna.tf32.f32 %0,%1;" : "=r"(u) : "f"(f)); return u;
}
// D(16x8,f32) += A(16x8,tf32 row) * B(8x8,tf32 col)
__device__ __forceinline__ void mma8(float* d, const u32* a, u32 b0, u32 b1){
    asm volatile("mma.sync.aligned.m16n8k8.row.col.f32.tf32.tf32.f32 "
        "{%0,%1,%2,%3}, {%4,%5,%6,%7}, {%8,%9}, {%0,%1,%2,%3};"
        : "+f"(d[0]), "+f"(d[1]), "+f"(d[2]), "+f"(d[3])
        : "r"(a[0]), "r"(a[1]), "r"(a[2]), "r"(a[3]), "r"(b0), "r"(b1));
}

// ===========================================================================
// K1: per (b,c,h): Y_diag -> Y, chunk states -> g_states. 128 thr = 4 warps.
// ===========================================================================
__global__ __launch_bounds__(128) void ssd_k1(
    const float* __restrict__ X, const float* __restrict__ A,
    const float* __restrict__ Bm, const float* __restrict__ Cm,
    float* __restrict__ Y)
{
    extern __shared__ float smf[];
    u32* sXt = (u32*)smf;              // [p][s] tf32
    u32* sB  = (u32*)smf + 64*RS;      // [s][n] tf32
    u32* sC  = (u32*)smf + 2*64*RS;    // [l][n] tf32; reused: sG [l][s]; sSt f32
    u32* sBt = (u32*)smf + 3*64*RS;    // [n][l] tf32 (dec[l] folded)
    float* aA   = smf + 4*64*RS;
    float* el   = aA + 64;
    float* einv = el + 64;
    float* decs = einv + 64;
    u32*   sG   = sC;
    float* sY   = (float*)sB;          // after mm1
    float* sSt  = (float*)sC;          // after mm2 (own rows only)

    const int h = blockIdx.x, c = blockIdx.y, b = blockIdx.z;
    const int tid = threadIdx.x, wid = tid >> 5, lane = tid & 31;
    const int qr = lane >> 2, qc = lane & 3;
    const int m0 = wid * 16;
    const int base = ((b*SEQ + c*LLC)*HH + h)*64;

    // phase 0: load tiles (tf32 convert), X transposed
    #pragma unroll
    for (int i = tid; i < 1024; i += 128) {
        int row = i >> 4, c4 = (i & 15) << 2;
        int g = base + row*GSTR + c4;
        float4 xv = *(const float4*)&X[g];
        float4 bv = *(const float4*)&Bm[g];
        float4 cv = *(const float4*)&Cm[g];
        *(uint4*)&sB[row*RS + c4] = make_uint4(cvt_tf32(bv.x), cvt_tf32(bv.y),
                                               cvt_tf32(bv.z), cvt_tf32(bv.w));
        *(uint4*)&sC[row*RS + c4] = make_uint4(cvt_tf32(cv.x), cvt_tf32(cv.y),
                                               cvt_tf32(cv.z), cvt_tf32(cv.w));
        sXt[(c4+0)*RS + row] = cvt_tf32(xv.x);
        sXt[(c4+1)*RS + row] = cvt_tf32(xv.y);
        sXt[(c4+2)*RS + row] = cvt_tf32(xv.z);
        sXt[(c4+3)*RS + row] = cvt_tf32(xv.w);
    }
    if (tid < 64) aA[tid] = A[(b*SEQ + c*LLC + tid)*HH + h];
    __syncthreads();

    if (tid < 64) {
        float s = 0.f, mine = 0.f;
        #pragma unroll
        for (int j = 0; j < 64; j++) { s += aA[j]; if (j == tid) mine = s; }
        el[tid]   = __expf(mine);
        einv[tid] = __expf(-mine);
        decs[tid] = __expf(s - mine);
    }
    __syncthreads();

    // build sBt[n][l] = tf32( B[l][n] * dec[l] )
    #pragma unroll
    for (int i = tid; i < 1024; i += 128) {
        int row = i >> 4, c4 = (i & 15) << 2;   // row = l
        float d = decs[row];
        uint4 bw = *(const uint4*)&sB[row*RS + c4];
        sBt[(c4+0)*RS + row] = cvt_tf32(__uint_as_float(bw.x)*d);
        sBt[(c4+1)*RS + row] = cvt_tf32(__uint_as_float(bw.y)*d);
        sBt[(c4+2)*RS + row] = cvt_tf32(__uint_as_float(bw.z)*d);
        sBt[(c4+3)*RS + row] = cvt_tf32(__uint_as_float(bw.w)*d);
    }

    // ---- mm1: G[l,s] = sum_n C[l,n]*B[s,n]; only s-tiles t <= 2w+1 ----
    float g[8][4] = {};
    const int nt1 = 2*wid + 2;
    #pragma unroll
    for (int kk = 0; kk < 8; kk++) {
        int k0 = kk*8;
        u32 a[4] = { sC[(m0+qr)*RS + k0+qc],   sC[(m0+qr+8)*RS + k0+qc],
                     sC[(m0+qr)*RS + k0+qc+4], sC[(m0+qr+8)*RS + k0+qc+4] };
        #pragma unroll
        for (int t = 0; t < 8; t++) {
            if (t < nt1) {
                u32 b0 = sB[(t*8+qr)*RS + k0+qc];
                u32 b1 = sB[(t*8+qr)*RS + k0+qc+4];
                mma8(g[t], a, b0, b1);
            }
        }
    }
    __syncthreads();   // all warps done reading sB/sC

    // mask + decay into sG[l][s] (own rows; warp-local ordering suffices)
    {
        const int l0 = m0 + qr, l1 = l0 + 8;
        const float e0 = el[l0], e1 = el[l1];
        #pragma unroll
        for (int t = 0; t < 8; t++) {
            if (t < nt1) {
                int s0 = t*8 + 2*qc;
                float i0 = einv[s0], i1 = einv[s0+1];
                float v0 = (s0   <= l0) ? g[t][0]*e0*i0 : 0.f;
                float v1 = (s0+1 <= l0) ? g[t][1]*e0*i1 : 0.f;
                float v2 = (s0   <= l1) ? g[t][2]*e1*i0 : 0.f;
                float v3 = (s0+1 <= l1) ? g[t][3]*e1*i1 : 0.f;
                *(uint2*)&sG[l0*RS + s0] = make_uint2(cvt_tf32(v0), cvt_tf32(v1));
                *(uint2*)&sG[l1*RS + s0] = make_uint2(cvt_tf32(v2), cvt_tf32(v3));
            }
        }
    }
    __syncwarp();

    // ---- mm2: Y[l,p] = sum_{s} G[l,s]*X[s,p]; k-steps kk <= 2w+1 ----
    float y[8][4] = {};
    #pragma unroll
    for (int kk = 0; kk < 8; kk++) {
        if (kk < nt1) {
            int k0 = kk*8;
            u32 a[4] = { sG[(m0+qr)*RS + k0+qc],   sG[(m0+qr+8)*RS + k0+qc],
                         sG[(m0+qr)*RS + k0+qc+4], sG[(m0+qr+8)*RS + k0+qc+4] };
            #pragma unroll
            for (int t = 0; t < 8; t++) {
                u32 b0 = sXt[(t*8+qr)*RS + k0+qc];
                u32 b1 = sXt[(t*8+qr)*RS + k0+qc+4];
                mma8(y[t], a, b0, b1);
            }
        }
    }

    // ---- mm3: S[p,n] = sum_l Xt[p,l]*(dec[l]*B[l,n]) ----
    float st[8][4] = {};
    #pragma unroll
    for (int kk = 0; kk < 8; kk++) {
        int k0 = kk*8;
        u32 a[4] = { sXt[(m0+qr)*RS + k0+qc],   sXt[(m0+qr+8)*RS + k0+qc],
                     sXt[(m0+qr)*RS + k0+qc+4], sXt[(m0+qr+8)*RS + k0+qc+4] };
        #pragma unroll
        for (int t = 0; t < 8; t++) {
            u32 b0 = sBt[(t*8+qr)*RS + k0+qc];
            u32 b1 = sBt[(t*8+qr)*RS + k0+qc+4];
            mma8(st[t], a, b0, b1);
        }
    }

    // stage Y (into sB space) and states (into own sG rows)
    #pragma unroll
    for (int t = 0; t < 8; t++) {
        int p0 = t*8 + 2*qc;
        *(float2*)&sY[(m0+qr)*RS + p0]   = make_float2(y[t][0], y[t][1]);
        *(float2*)&sY[(m0+qr+8)*RS + p0] = make_float2(y[t][2], y[t][3]);
        *(float2*)&sSt[(m0+qr)*RS + p0]   = make_float2(st[t][0], st[t][1]);
        *(float2*)&sSt[(m0+qr+8)*RS + p0] = make_float2(st[t][2], st[t][3]);
    }
    __syncthreads();

    // coalesced copy-out
    const int sbase = ((b*CC + c)*HH + h)*4096;
    #pragma unroll
    for (int i = tid; i < 1024; i += 128) {
        int row = i >> 4, c4 = (i & 15) << 2;
        *(float4*)&Y[base + row*GSTR + c4] = *(const float4*)&sY[row*RS + c4];
        *(float4*)&g_states[sbase + row*64 + c4] = *(const float4*)&sSt[row*RS + c4];
    }
}

// ===========================================================================
// K2: inter-chunk scan, 512 blocks (8 segments per (b,h)), prefetched
// ===========================================================================
__global__ __launch_bounds__(512) void ssd_k2(const float* __restrict__ A)
{
    __shared__ float ea[CC];
    const int blk = blockIdx.x;
    const int seg = blk & 7, bh = blk >> 3, h = bh & 31, b = bh >> 5;
    const int tid = threadIdx.x;

    if (tid < CC) {
        float s = 0.f;
        int ab = (b*SEQ + tid*LLC)*HH + h;
        for (int l = 0; l < LLC; l++) s += A[ab + l*HH];
        ea[tid] = __expf(s);
    }
    __syncthreads();

    const int e = seg*512 + tid;
    size_t off = ((size_t)(b*CC)*HH + h)*4096 + e;
    float run = 0.f;
    float v = g_states[off];
    for (int z = 0; z < CC; z++) {
        float nv = (z+1 < CC) ? g_states[off + (size_t)HH*4096] : 0.f;
        g_prefix[off] = run;
        run = run*ea[z] + v;
        v = nv;
        off += (size_t)HH*4096;
    }
}

// ===========================================================================
// K3: Y[l,p] += el[l] * sum_n C[l,n]*St[p,n]
// ===========================================================================
__global__ __launch_bounds__(128) void ssd_k3(
    const float* __restrict__ A, const float* __restrict__ Cm,
    float* __restrict__ Y)
{
    extern __shared__ float smf[];
    u32* sC = (u32*)smf;               // [l][n] tf32; reused f32 Y-stage
    u32* sS = (u32*)smf + 64*RS;       // [p][n] tf32
    float* aA = smf + 2*64*RS;
    float* el = aA + 64;
    float* sY = (float*)sC;

    const int h = blockIdx.x, c = blockIdx.y, b = blockIdx.z;
    const int tid = threadIdx.x, wid = tid >> 5, lane = tid & 31;
    const int qr = lane >> 2, qc = lane & 3;
    const int m0 = wid * 16;
    const int base = ((b*SEQ + c*LLC)*HH + h)*64;
    const int sbase = ((b*CC + c)*HH + h)*4096;

    #pragma unroll
    for (int i = tid; i < 1024; i += 128) {
        int row = i >> 4, c4 = (i & 15) << 2;
        float4 cv = *(const float4*)&Cm[base + row*GSTR + c4];
        float4 sv = *(const float4*)&g_prefix[sbase + row*64 + c4];
        *(uint4*)&sC[row*RS + c4] = make_uint4(cvt_tf32(cv.x), cvt_tf32(cv.y),
                                               cvt_tf32(cv.z), cvt_tf32(cv.w));
        *(uint4*)&sS[row*RS + c4] = make_uint4(cvt_tf32(sv.x), cvt_tf32(sv.y),
                                               cvt_tf32(sv.z), cvt_tf32(sv.w));
    }
    if (tid < 64) aA[tid] = A[(b*SEQ + c*LLC + tid)*HH + h];
    __syncthreads();
    if (tid < 64) {
        float s = 0.f, mine = 0.f;
        #pragma unroll
        for (int j = 0; j < 64; j++) { s += aA[j]; if (j == tid) mine = s; }
        el[tid] = __expf(mine);
    }
    __syncthreads();

    float y[8][4] = {};
    #pragma unroll
    for (int kk = 0; kk < 8; kk++) {
        int k0 = kk*8;
        u32 a[4] = { sC[(m0+qr)*RS + k0+qc],   sC[(m0+qr+8)*RS + k0+qc],
                     sC[(m0+qr)*RS + k0+qc+4], sC[(m0+qr+8)*RS + k0+qc+4] };
        #pragma unroll
        for (int t = 0; t < 8; t++) {
            u32 b0 = sS[(t*8+qr)*RS + k0+qc];
            u32 b1 = sS[(t*8+qr)*RS + k0+qc+4];
            mma8(y[t], a, b0, b1);
        }
    }
    __syncthreads();   // all warps done reading sC before restage

    {
        const int l0 = m0 + qr, l1 = l0 + 8;
        const float e0 = el[l0], e1 = el[l1];
        #pragma unroll
        for (int t = 0; t < 8; t++) {
            int p0 = t*8 + 2*qc;
            *(float2*)&sY[l0*RS + p0] = make_float2(e0*y[t][0], e0*y[t][1]);
            *(float2*)&sY[l1*RS + p0] = make_float2(e1*y[t][2], e1*y[t][3]);
        }
    }
    __syncthreads();

    #pragma unroll
    for (int i = tid; i < 1024; i += 128) {
        int row = i >> 4, c4 = (i & 15) << 2;
        float4 o = *(float4*)&Y[base + row*GSTR + c4];
        float4 a4 = *(const float4*)&sY[row*RS + c4];
        o.x += a4.x; o.y += a4.y; o.z += a4.z; o.w += a4.w;
        *(float4*)&Y[base + row*GSTR + c4] = o;
    }
}

// ---------------------------------------------------------------------------
extern "C" void kernel_launch(void* const* d_in, const int* in_sizes, int n_in,
                              void* d_out, int out_size)
{
    const float* X  = (const float*)d_in[0];
    const float* A  = (const float*)d_in[1];
    const float* Bm = (const float*)d_in[2];
    const float* Cm = (const float*)d_in[3];
    float* Y = (float*)d_out;

    const int sm1 = (4*64*RS + 4*64) * 4;   // 70656 B
    const int sm3 = (2*64*RS + 2*64) * 4;   // 35328 B
    cudaFuncSetAttribute(ssd_k1, cudaFuncAttributeMaxDynamicSharedMemorySize, sm1);
    cudaFuncSetAttribute(ssd_k3, cudaFuncAttributeMaxDynamicSharedMemorySize, sm3);

    dim3 grid(HH, CC, BS);
    ssd_k1<<<grid, 128, sm1>>>(X, A, Bm, Cm, Y);
    ssd_k2<<<BS*HH*8, 512>>>(A);
    ssd_k3<<<grid, 128, sm3>>>(A, Cm, Y);
}

// round 7
// speedup vs baseline: 2.2036x; 1.0743x over previous
#include <cuda_runtime.h>
#include <cstdint>

#define BS   2
#define SEQ  4096
#define HH   32
#define LLC  64
#define CC   (SEQ/LLC)   // 64
#define RS   72          // smem row stride in 4B words
#define GSTR (HH*64)

__device__ float g_states[(size_t)BS*CC*HH*64*64]; // [b][c][h][p][n]
__device__ float g_prefix[(size_t)BS*CC*HH*64*64];

typedef unsigned int u32;

__device__ __forceinline__ u32 cvt_tf32(float f){
    u32 u; asm("cvt.rna.tf32.f32 %0,%1;" : "=r"(u) : "f"(f)); return u;
}
// D(16x8,f32) += A(16x8,tf32 row) * B(8x8,tf32 col)
__device__ __forceinline__ void mma8(float* d, const u32* a, u32 b0, u32 b1){
    asm volatile("mma.sync.aligned.m16n8k8.row.col.f32.tf32.tf32.f32 "
        "{%0,%1,%2,%3}, {%4,%5,%6,%7}, {%8,%9}, {%0,%1,%2,%3};"
        : "+f"(d[0]), "+f"(d[1]), "+f"(d[2]), "+f"(d[3])
        : "r"(a[0]), "r"(a[1]), "r"(a[2]), "r"(a[3]), "r"(b0), "r"(b1));
}

// skewed-paired layout: element (r,k) at word r*RS + W(r,k).
// pair q = 4*(k>>3) + (k&3)  (q in [0,32)) holds k (slot (k>>2)&1 == 0) and
// k+4 (slot 1); pair column rotated by r>>2 to kill transpose-write conflicts.
__device__ __forceinline__ int Wf(int r, int k){
    return 2*(((4*(k>>3)) + (k&3) + (r>>2)) & 31) + ((k>>2)&1);
}
__device__ __forceinline__ void stp(u32* t, int r, int k, u32 v){
    t[r*RS + Wf(r,k)] = v;
}
// LDS.64 of pair (8kk+qc, 8kk+qc+4) from row r
__device__ __forceinline__ uint2 ldpair(const u32* t, int r, int kk, int qc){
    return *(const uint2*)&t[r*RS + 2*((4*kk + qc + (r>>2)) & 31)];
}

// ===========================================================================
// K1: per (b,c,h): Y_diag -> Y, chunk states -> g_states. 128 thr = 4 warps.
// ===========================================================================
__global__ __launch_bounds__(128) void ssd_k1(
    const float* __restrict__ X, const float* __restrict__ A,
    const float* __restrict__ Bm, const float* __restrict__ Cm,
    float* __restrict__ Y)
{
    extern __shared__ float smf[];
    u32* sXt = (u32*)smf;              // [p][s]  skew-paired
    u32* sB  = (u32*)smf + 64*RS;      // [s][n]  skew-paired; reused: sY (plain)
    u32* sC  = (u32*)smf + 2*64*RS;    // [l][n]  skew-paired; reused: sG, sSt(plain)
    u32* sBt = (u32*)smf + 3*64*RS;    // [n][l]  skew-paired (dec folded)
    float* aA   = smf + 4*64*RS;
    float* el   = aA + 64;
    float* einv = el + 64;
    float* decs = einv + 64;
    u32*   sG   = sC;
    float* sY   = (float*)sB;
    float* sSt  = (float*)sC;

    const int h = blockIdx.x, c = blockIdx.y, b = blockIdx.z;
    const int tid = threadIdx.x, wid = tid >> 5, lane = tid & 31;
    const int qr = lane >> 2, qc = lane & 3;
    const int m0 = wid * 16;
    const int base = ((b*SEQ + c*LLC)*HH + h)*64;

    // phase 0: load tiles (tf32), X transposed into sXt
    #pragma unroll
    for (int i = tid; i < 1024; i += 128) {
        int row = i >> 4, c4 = (i & 15) << 2;
        int g = base + row*GSTR + c4;
        float4 xv = *(const float4*)&X[g];
        float4 bv = *(const float4*)&Bm[g];
        float4 cv = *(const float4*)&Cm[g];
        stp(sB, row, c4+0, cvt_tf32(bv.x)); stp(sB, row, c4+1, cvt_tf32(bv.y));
        stp(sB, row, c4+2, cvt_tf32(bv.z)); stp(sB, row, c4+3, cvt_tf32(bv.w));
        stp(sC, row, c4+0, cvt_tf32(cv.x)); stp(sC, row, c4+1, cvt_tf32(cv.y));
        stp(sC, row, c4+2, cvt_tf32(cv.z)); stp(sC, row, c4+3, cvt_tf32(cv.w));
        stp(sXt, c4+0, row, cvt_tf32(xv.x)); stp(sXt, c4+1, row, cvt_tf32(xv.y));
        stp(sXt, c4+2, row, cvt_tf32(xv.z)); stp(sXt, c4+3, row, cvt_tf32(xv.w));
    }
    if (tid < 64) aA[tid] = A[(b*SEQ + c*LLC + tid)*HH + h];
    __syncthreads();

    if (tid < 64) {
        float s = 0.f, mine = 0.f;
        #pragma unroll
        for (int j = 0; j < 64; j++) { s += aA[j]; if (j == tid) mine = s; }
        el[tid]   = __expf(mine);
        einv[tid] = __expf(-mine);
        decs[tid] = __expf(s - mine);
    }
    __syncthreads();

    // build sBt[n][l] = tf32( B[l][n]*dec[l] ): 64 rows x 32 pairs
    #pragma unroll
    for (int i = tid; i < 2048; i += 128) {
        int l = i >> 5, q = i & 31;
        uint2 bb = *(const uint2*)&sB[l*RS + 2*((q + (l>>2)) & 31)];
        int n_lo = 8*(q>>2) + (q&3), n_hi = n_lo + 4;
        float d = decs[l];
        stp(sBt, n_lo, l, cvt_tf32(__uint_as_float(bb.x)*d));
        stp(sBt, n_hi, l, cvt_tf32(__uint_as_float(bb.y)*d));
    }
    __syncthreads();

    // ---- mm1: G[l,s] = sum_n C[l,n]*B[s,n] ----
    float g[8][4] = {};
    #pragma unroll
    for (int kk = 0; kk < 8; kk++) {
        uint2 alo = ldpair(sC, m0+qr,   kk, qc);
        uint2 ahi = ldpair(sC, m0+qr+8, kk, qc);
        u32 a[4] = { alo.x, ahi.x, alo.y, ahi.y };
        #pragma unroll
        for (int t = 0; t < 8; t++) {
            uint2 bb = ldpair(sB, t*8+qr, kk, qc);
            mma8(g[t], a, bb.x, bb.y);
        }
    }
    __syncthreads();   // all warps done reading sB/sC

    // mask + decay into sG (own rows)
    {
        const int l0 = m0 + qr, l1 = l0 + 8;
        const float e0 = el[l0], e1 = el[l1];
        #pragma unroll
        for (int t = 0; t < 8; t++) {
            int s0 = t*8 + 2*qc, s1 = s0 + 1;
            float i0 = einv[s0], i1 = einv[s1];
            float v0 = (s0 <= l0) ? g[t][0]*e0*i0 : 0.f;
            float v1 = (s1 <= l0) ? g[t][1]*e0*i1 : 0.f;
            float v2 = (s0 <= l1) ? g[t][2]*e1*i0 : 0.f;
            float v3 = (s1 <= l1) ? g[t][3]*e1*i1 : 0.f;
            stp(sG, l0, s0, cvt_tf32(v0)); stp(sG, l0, s1, cvt_tf32(v1));
            stp(sG, l1, s0, cvt_tf32(v2)); stp(sG, l1, s1, cvt_tf32(v3));
        }
    }
    __syncwarp();

    // ---- mm2: Y[l,p] = sum_s G[l,s]*X[s,p] ----
    float y[8][4] = {};
    #pragma unroll
    for (int kk = 0; kk < 8; kk++) {
        uint2 alo = ldpair(sG, m0+qr,   kk, qc);
        uint2 ahi = ldpair(sG, m0+qr+8, kk, qc);
        u32 a[4] = { alo.x, ahi.x, alo.y, ahi.y };
        #pragma unroll
        for (int t = 0; t < 8; t++) {
            uint2 bb = ldpair(sXt, t*8+qr, kk, qc);
            mma8(y[t], a, bb.x, bb.y);
        }
    }

    // ---- mm3: S[p,n] = sum_l Xt[p,l]*(dec[l]*B[l,n]) ----
    float st[8][4] = {};
    #pragma unroll
    for (int kk = 0; kk < 8; kk++) {
        uint2 alo = ldpair(sXt, m0+qr,   kk, qc);
        uint2 ahi = ldpair(sXt, m0+qr+8, kk, qc);
        u32 a[4] = { alo.x, ahi.x, alo.y, ahi.y };
        #pragma unroll
        for (int t = 0; t < 8; t++) {
            uint2 bb = ldpair(sBt, t*8+qr, kk, qc);
            mma8(st[t], a, bb.x, bb.y);
        }
    }
    __syncwarp();   // own-row sG reads done before sSt overwrite

    // stage results (plain row-major, stride RS)
    #pragma unroll
    for (int t = 0; t < 8; t++) {
        int p0 = t*8 + 2*qc;
        *(float2*)&sY[(m0+qr)*RS + p0]    = make_float2(y[t][0], y[t][1]);
        *(float2*)&sY[(m0+qr+8)*RS + p0]  = make_float2(y[t][2], y[t][3]);
        *(float2*)&sSt[(m0+qr)*RS + p0]   = make_float2(st[t][0], st[t][1]);
        *(float2*)&sSt[(m0+qr+8)*RS + p0] = make_float2(st[t][2], st[t][3]);
    }
    __syncthreads();

    const int sbase = ((b*CC + c)*HH + h)*4096;
    #pragma unroll
    for (int i = tid; i < 1024; i += 128) {
        int row = i >> 4, c4 = (i & 15) << 2;
        *(float4*)&Y[base + row*GSTR + c4] = *(const float4*)&sY[row*RS + c4];
        *(float4*)&g_states[sbase + row*64 + c4] = *(const float4*)&sSt[row*RS + c4];
    }
}

// ===========================================================================
// K2: inter-chunk scan, 512 blocks (8 segments per (b,h)), prefetched
// ===========================================================================
__global__ __launch_bounds__(512) void ssd_k2(const float* __restrict__ A)
{
    __shared__ float ea[CC];
    const int blk = blockIdx.x;
    const int seg = blk & 7, bh = blk >> 3, h = bh & 31, b = bh >> 5;
    const int tid = threadIdx.x;

    if (tid < CC) {
        float s = 0.f;
        int ab = (b*SEQ + tid*LLC)*HH + h;
        for (int l = 0; l < LLC; l++) s += A[ab + l*HH];
        ea[tid] = __expf(s);
    }
    __syncthreads();

    const int e = seg*512 + tid;
    size_t off = ((size_t)(b*CC)*HH + h)*4096 + e;
    float run = 0.f;
    float v = g_states[off];
    for (int z = 0; z < CC; z++) {
        float nv = (z+1 < CC) ? g_states[off + (size_t)HH*4096] : 0.f;
        g_prefix[off] = run;
        run = run*ea[z] + v;
        v = nv;
        off += (size_t)HH*4096;
    }
}

// ===========================================================================
// K3: Y[l,p] += el[l] * sum_n C[l,n]*St[p,n]
// ===========================================================================
__global__ __launch_bounds__(128) void ssd_k3(
    const float* __restrict__ A, const float* __restrict__ Cm,
    float* __restrict__ Y)
{
    extern __shared__ float smf[];
    u32* sC = (u32*)smf;               // [l][n] skew-paired; reused: sY plain
    u32* sS = (u32*)smf + 64*RS;       // [p][n] skew-paired
    float* aA = smf + 2*64*RS;
    float* el = aA + 64;
    float* sY = (float*)sC;

    const int h = blockIdx.x, c = blockIdx.y, b = blockIdx.z;
    const int tid = threadIdx.x, wid = tid >> 5, lane = tid & 31;
    const int qr = lane >> 2, qc = lane & 3;
    const int m0 = wid * 16;
    const int base = ((b*SEQ + c*LLC)*HH + h)*64;
    const int sbase = ((b*CC + c)*HH + h)*4096;

    #pragma unroll
    for (int i = tid; i < 1024; i += 128) {
        int row = i >> 4, c4 = (i & 15) << 2;
        float4 cv = *(const float4*)&Cm[base + row*GSTR + c4];
        float4 sv = *(const float4*)&g_prefix[sbase + row*64 + c4];
        stp(sC, row, c4+0, cvt_tf32(cv.x)); stp(sC, row, c4+1, cvt_tf32(cv.y));
        stp(sC, row, c4+2, cvt_tf32(cv.z)); stp(sC, row, c4+3, cvt_tf32(cv.w));
        stp(sS, row, c4+0, cvt_tf32(sv.x)); stp(sS, row, c4+1, cvt_tf32(sv.y));
        stp(sS, row, c4+2, cvt_tf32(sv.z)); stp(sS, row, c4+3, cvt_tf32(sv.w));
    }
    if (tid < 64) aA[tid] = A[(b*SEQ + c*LLC + tid)*HH + h];
    __syncthreads();
    if (tid < 64) {
        float s = 0.f, mine = 0.f;
        #pragma unroll
        for (int j = 0; j < 64; j++) { s += aA[j]; if (j == tid) mine = s; }
        el[tid] = __expf(mine);
    }
    __syncthreads();

    float y[8][4] = {};
    #pragma unroll
    for (int kk = 0; kk < 8; kk++) {
        uint2 alo = ldpair(sC, m0+qr,   kk, qc);
        uint2 ahi = ldpair(sC, m0+qr+8, kk, qc);
        u32 a[4] = { alo.x, ahi.x, alo.y, ahi.y };
        #pragma unroll
        for (int t = 0; t < 8; t++) {
            uint2 bb = ldpair(sS, t*8+qr, kk, qc);
            mma8(y[t], a, bb.x, bb.y);
        }
    }
    __syncthreads();   // all reads of sC done before restage

    {
        const int l0 = m0 + qr, l1 = l0 + 8;
        const float e0 = el[l0], e1 = el[l1];
        #pragma unroll
        for (int t = 0; t < 8; t++) {
            int p0 = t*8 + 2*qc;
            *(float2*)&sY[l0*RS + p0] = make_float2(e0*y[t][0], e0*y[t][1]);
            *(float2*)&sY[l1*RS + p0] = make_float2(e1*y[t][2], e1*y[t][3]);
        }
    }
    __syncthreads();

    #pragma unroll
    for (int i = tid; i < 1024; i += 128) {
        int row = i >> 4, c4 = (i & 15) << 2;
        float4 o = *(float4*)&Y[base + row*GSTR + c4];
        float4 a4 = *(const float4*)&sY[row*RS + c4];
        o.x += a4.x; o.y += a4.y; o.z += a4.z; o.w += a4.w;
        *(float4*)&Y[base + row*GSTR + c4] = o;
    }
}

// ---------------------------------------------------------------------------
extern "C" void kernel_launch(void* const* d_in, const int* in_sizes, int n_in,
                              void* d_out, int out_size)
{
    const float* X  = (const float*)d_in[0];
    const float* A  = (const float*)d_in[1];
    const float* Bm = (const float*)d_in[2];
    const float* Cm = (const float*)d_in[3];
    float* Y = (float*)d_out;

    const int sm1 = (4*64*RS + 4*64) * 4;   // 74752 B -> 3 blocks/SM
    const int sm3 = (2*64*RS + 2*64) * 4;   // 37376 B -> 6 blocks/SM
    cudaFuncSetAttribute(ssd_k1, cudaFuncAttributeMaxDynamicSharedMemorySize, sm1);
    cudaFuncSetAttribute(ssd_k3, cudaFuncAttributeMaxDynamicSharedMemorySize, sm3);

    dim3 grid(HH, CC, BS);
    ssd_k1<<<grid, 128, sm1>>>(X, A, Bm, Cm, Y);
    ssd_k2<<<BS*HH*8, 512>>>(A);
    ssd_k3<<<grid, 128, sm3>>>(A, Cm, Y);
}